// round 5
// baseline (speedup 1.0000x reference)
#include <cuda_runtime.h>
#include <cuda_bf16.h>
#include <math.h>
#include <stdint.h>

#define NN 10000
#define EE 320000

// ---------------- scratch (static device globals; no allocation) ----------------
__device__ int   g_is64;
__device__ int   g_srcE[EE];
__device__ int   g_dstE[EE];
__device__ int   g_srcSorted[EE];
__device__ int   g_degi[NN];
__device__ int   g_cnt[NN];
__device__ int   g_off[NN + 1];
__device__ __nv_bfloat16 g_Ab[(size_t)NN * 2048];    // [hi(1024) | lo(1024)] per row
__device__ __nv_bfloat16 g_Wtb[(size_t)1024 * 2048]; // W^T: row j'(out col), [hi|lo]
__device__ float g_bias[1024];                       // bx_l + bh_l + b, in j' order

__device__ __forceinline__ uint32_t smem_u32(const void* p) {
    uint32_t a;
    asm("{ .reg .u64 t; cvta.to.shared.u64 t, %1; cvt.u32.u64 %0, t; }" : "=r"(a) : "l"(p));
    return a;
}

// ---------------- edge dtype detection (int32 vs int64) ----------------
__global__ void k_detect(const unsigned* __restrict__ w) {
    unsigned bad = 0;
    #pragma unroll
    for (int i = 0; i < 64; i++) bad |= w[2 * i + 1];
    g_is64 = (bad == 0) ? 1 : 0;
}

__global__ void k_convert(const void* __restrict__ ei) {
    int e = blockIdx.x * blockDim.x + threadIdx.x;
    if (e < NN) { g_degi[e] = 0; g_cnt[e] = 0; }
    if (e >= EE) return;
    int src, dst;
    if (g_is64) {
        const long long* p = (const long long*)ei;
        src = (int)p[e]; dst = (int)p[EE + e];
    } else {
        const int* p = (const int*)ei;
        src = p[e]; dst = p[EE + e];
    }
    g_srcE[e] = src; g_dstE[e] = dst;
}

__global__ void k_hist() {
    int e = blockIdx.x * blockDim.x + threadIdx.x;
    if (e < EE) atomicAdd(&g_degi[g_dstE[e]], 1);
}

// warp-shuffle scan: 1024 threads, 10 elems/thread
__global__ void k_scan() {
    __shared__ int warpsum[32];
    int t = threadIdx.x;
    int lane = t & 31, w = t >> 5;
    const int CH = 10;
    int base = t * CH;
    int v[CH];
    int loc = 0;
    #pragma unroll
    for (int i = 0; i < CH; i++) {
        int idx = base + i;
        v[i] = (idx < NN) ? g_degi[idx] : 0;
        loc += v[i];
    }
    int s = loc;
    #pragma unroll
    for (int off = 1; off < 32; off <<= 1) {
        int u = __shfl_up_sync(0xffffffffu, s, off);
        if (lane >= off) s += u;
    }
    if (lane == 31) warpsum[w] = s;
    __syncthreads();
    if (w == 0) {
        int ws = warpsum[lane];
        #pragma unroll
        for (int off = 1; off < 32; off <<= 1) {
            int u = __shfl_up_sync(0xffffffffu, ws, off);
            if (lane >= off) ws += u;
        }
        warpsum[lane] = ws;
    }
    __syncthreads();
    int wbase = (w > 0) ? warpsum[w - 1] : 0;
    int run = wbase + s - loc;  // exclusive prefix
    #pragma unroll
    for (int i = 0; i < CH; i++) {
        int idx = base + i;
        if (idx < NN) { g_off[idx] = run; run += v[i]; }
    }
    if (t == 1023) g_off[NN] = run;
}

__global__ void k_scatter() {
    int e = blockIdx.x * blockDim.x + threadIdx.x;
    if (e >= EE) return;
    int d = g_dstE[e];
    int pos = g_off[d] + atomicAdd(&g_cnt[d], 1);
    g_srcSorted[pos] = g_srcE[e];
}

// ---------------- aggregation + split-bf16 A packing ----------------
__device__ __forceinline__ void split_store(__nv_bfloat16* p, size_t hi_idx, float v) {
    __nv_bfloat16 hi = __float2bfloat16(v);
    float r = v - __bfloat162float(hi);
    p[hi_idx] = hi;
    p[hi_idx + 1024] = __float2bfloat16(r);
}

// 128 threads: t<64 -> X float4-chunk t ; t>=64 -> h float4-chunk t-64
__global__ __launch_bounds__(128) void k_agg(const float* __restrict__ X,
                                             const float* __restrict__ h) {
    __shared__ int sidx[128];
    int n = blockIdx.x, t = threadIdx.x;
    int s0 = g_off[n], s1 = g_off[n + 1];
    const float* basep = (t < 64) ? X : h;
    int q = (t & 63) * 4;
    float ax = 0.f, ay = 0.f, az = 0.f, aw = 0.f;
    for (int bs = s0; bs < s1; bs += 128) {
        int cnt = min(128, s1 - bs);
        if (t < cnt) sidx[t] = g_srcSorted[bs + t];
        __syncthreads();
        int j = 0;
        for (; j + 4 <= cnt; j += 4) {
            float4 a = *(const float4*)(basep + (size_t)sidx[j]     * 256 + q);
            float4 b2 = *(const float4*)(basep + (size_t)sidx[j + 1] * 256 + q);
            float4 c2 = *(const float4*)(basep + (size_t)sidx[j + 2] * 256 + q);
            float4 d2 = *(const float4*)(basep + (size_t)sidx[j + 3] * 256 + q);
            ax += a.x + b2.x + c2.x + d2.x;
            ay += a.y + b2.y + c2.y + d2.y;
            az += a.z + b2.z + c2.z + d2.z;
            aw += a.w + b2.w + c2.w + d2.w;
        }
        for (; j < cnt; j++) {
            float4 a = *(const float4*)(basep + (size_t)sidx[j] * 256 + q);
            ax += a.x; ay += a.y; az += a.z; aw += a.w;
        }
        __syncthreads();
    }
    int deg = s1 - s0;
    float inv = 1.f / (float)(deg > 0 ? deg : 1);
    float4 self = *(const float4*)(basep + (size_t)n * 256 + q);
    size_t o = (size_t)n * 2048;
    int seg = (t < 64) ? 0 : 512;  // aggX cols 0-255, X 256-511, aggH 512-767, h 768-1023
    split_store(g_Ab, o + seg + q + 0, ax * inv);
    split_store(g_Ab, o + seg + q + 1, ay * inv);
    split_store(g_Ab, o + seg + q + 2, az * inv);
    split_store(g_Ab, o + seg + q + 3, aw * inv);
    split_store(g_Ab, o + seg + 256 + q + 0, self.x);
    split_store(g_Ab, o + seg + 256 + q + 1, self.y);
    split_store(g_Ab, o + seg + 256 + q + 2, self.z);
    split_store(g_Ab, o + seg + 256 + q + 3, self.w);
}

// ---------------- weight packing: col order j' = 4*e + gate ----------------
__global__ void k_packWt(const float* __restrict__ Wx_l, const float* __restrict__ Wx_r,
                         const float* __restrict__ Wh_l, const float* __restrict__ Wh_r,
                         const float* __restrict__ bx_l, const float* __restrict__ bh_l,
                         const float* __restrict__ bb) {
    int idx = blockIdx.x * blockDim.x + threadIdx.x;
    if (idx >= 1024 * 1024) return;
    int d = idx & 1023;      // K row
    int jp = idx >> 10;      // output col (interleaved)
    int e = jp >> 2, k = jp & 3;
    int seg = d >> 8, dd = d & 255;
    const float* src = (seg == 0) ? Wx_l : (seg == 1) ? Wx_r : (seg == 2) ? Wh_l : Wh_r;
    float w = src[k * 65536 + dd * 256 + e];
    split_store(g_Wtb, (size_t)jp * 2048 + d, w);
    if (d == 0)
        g_bias[jp] = bx_l[k * 256 + e] + bh_l[k * 256 + e] + bb[k * 256 + e];
}

// ---------------- mma.sync bf16 GEMM + fused gates ----------------
#define BM 128
#define BN 128
#define NITER 48   // 3 segments * 1024 / 64
#define TILE_B 16384
#define STAGE_B (2 * TILE_B)
#define DYN_SMEM (3 * STAGE_B)

#define LDSM_X4(r0, r1, r2, r3, addr) \
    asm volatile("ldmatrix.sync.aligned.m8n8.x4.shared.b16 {%0,%1,%2,%3}, [%4];" \
                 : "=r"(r0), "=r"(r1), "=r"(r2), "=r"(r3) : "r"(addr))

#define MMA16816(d, a0, a1, a2, a3, b0, b1) \
    asm volatile("mma.sync.aligned.m16n8k16.row.col.f32.bf16.bf16.f32 " \
                 "{%0,%1,%2,%3}, {%4,%5,%6,%7}, {%8,%9}, {%0,%1,%2,%3};" \
                 : "+f"((d)[0]), "+f"((d)[1]), "+f"((d)[2]), "+f"((d)[3]) \
                 : "r"(a0), "r"(a1), "r"(a2), "r"(a3), "r"(b0), "r"(b1))

__device__ __forceinline__ void issue_tile(uint32_t sA, uint32_t sB, int m0, int n0,
                                           int it, int tid) {
    int k0 = it * 64;
    int seg = k0 >> 10, kk = k0 & 1023;
    int acol = kk + (seg == 2 ? 1024 : 0);
    int bcol = kk + (seg == 1 ? 1024 : 0);
    #pragma unroll
    for (int i = 0; i < 4; i++) {
        int ch = tid + i * 256;
        int row = ch >> 3, c = ch & 7;
        uint32_t so = row * 128 + ((c ^ (row & 7)) << 4);
        const __nv_bfloat16* ga = g_Ab + (size_t)(m0 + row) * 2048 + acol + c * 8;
        unsigned sz = (m0 + row < NN) ? 16u : 0u;
        asm volatile("cp.async.cg.shared.global [%0], [%1], 16, %2;"
                     :: "r"(sA + so), "l"(ga), "r"(sz));
        const __nv_bfloat16* gb = g_Wtb + (size_t)(n0 + row) * 2048 + bcol + c * 8;
        asm volatile("cp.async.cg.shared.global [%0], [%1], 16;"
                     :: "r"(sB + so), "l"(gb));
    }
}

__device__ __forceinline__ float fsigmoid(float x) { return 1.f / (1.f + __expf(-x)); }
__device__ __forceinline__ float ftanh(float x) {
    float e = __expf(-2.f * x);
    return (1.f - e) / (1.f + e);
}

__global__ __launch_bounds__(256) void k_mma(const float* __restrict__ cptr,
                                             const float* __restrict__ wcp,
                                             float* __restrict__ out) {
    extern __shared__ char smem[];
    uint32_t sb = smem_u32(smem);
    int tid = threadIdx.x;
    int lane = tid & 31, wid = tid >> 5;
    int warp_m = wid & 3, warp_n = wid >> 2;
    int m0 = blockIdx.y * BM, n0 = blockIdx.x * BN;
    int e0 = n0 >> 2;  // 32 features per col tile

    float acc[2][8][4];
    #pragma unroll
    for (int i = 0; i < 2; i++)
        #pragma unroll
        for (int j = 0; j < 8; j++)
            #pragma unroll
            for (int r = 0; r < 4; r++) acc[i][j][r] = 0.f;

    uint32_t sA[3], sB[3];
    #pragma unroll
    for (int s = 0; s < 3; s++) { sA[s] = sb + s * STAGE_B; sB[s] = sA[s] + TILE_B; }

    issue_tile(sA[0], sB[0], m0, n0, 0, tid);
    asm volatile("cp.async.commit_group;" ::: "memory");
    issue_tile(sA[1], sB[1], m0, n0, 1, tid);
    asm volatile("cp.async.commit_group;" ::: "memory");

    // ldmatrix address invariants
    int rowA[2], rowA7[2];
    #pragma unroll
    for (int mi = 0; mi < 2; mi++) {
        int r = warp_m * 32 + mi * 16 + (lane & 15);
        rowA[mi] = r * 128;
        rowA7[mi] = r & 7;
    }
    int achk = lane >> 4;
    int local = lane & 7, quad = lane >> 3;
    int bchk = quad & 1;
    int rowB[4], rowB7[4];
    #pragma unroll
    for (int np = 0; np < 4; np++) {
        int r = warp_n * 64 + np * 16 + ((quad >> 1) << 3) + local;
        rowB[np] = r * 128;
        rowB7[np] = r & 7;
    }

    for (int it = 0; it < NITER; it++) {
        asm volatile("cp.async.wait_group 1;" ::: "memory");
        __syncthreads();
        if (it + 2 < NITER)
            issue_tile(sA[(it + 2) % 3], sB[(it + 2) % 3], m0, n0, it + 2, tid);
        asm volatile("cp.async.commit_group;" ::: "memory");
        int s = it % 3;
        uint32_t Ab = sA[s], Bb = sB[s];
        #pragma unroll
        for (int ks = 0; ks < 4; ks++) {
            uint32_t a[2][4];
            #pragma unroll
            for (int mi = 0; mi < 2; mi++) {
                uint32_t ad = Ab + rowA[mi] + ((((ks * 2 + achk)) ^ rowA7[mi]) << 4);
                LDSM_X4(a[mi][0], a[mi][1], a[mi][2], a[mi][3], ad);
            }
            #pragma unroll
            for (int np = 0; np < 4; np++) {
                uint32_t bd = Bb + rowB[np] + ((((ks * 2 + bchk)) ^ rowB7[np]) << 4);
                uint32_t t0, t1, t2, t3;
                LDSM_X4(t0, t1, t2, t3, bd);
                MMA16816(acc[0][np * 2],     a[0][0], a[0][1], a[0][2], a[0][3], t0, t1);
                MMA16816(acc[1][np * 2],     a[1][0], a[1][1], a[1][2], a[1][3], t0, t1);
                MMA16816(acc[0][np * 2 + 1], a[0][0], a[0][1], a[0][2], a[0][3], t2, t3);
                MMA16816(acc[1][np * 2 + 1], a[1][0], a[1][1], a[1][2], a[1][3], t2, t3);
            }
        }
    }
    __syncthreads();  // done with pipeline smem

    // -------- fused gate epilogue --------
    // smem reuse: cbuf[128][36], oO/oH/oC[128][36], wcb[3][32]
    float* cbuf = (float*)smem;
    float* oO = (float*)(smem + 18432);
    float* oH = (float*)(smem + 36864);
    float* oC = (float*)(smem + 55296);
    float* wcb = (float*)(smem + 73728);

    for (int i = tid; i < 128 * 8; i += 256) {
        int r = i >> 3, q = i & 7;
        float4 v = make_float4(0.f, 0.f, 0.f, 0.f);
        if (m0 + r < NN) v = *(const float4*)(cptr + (size_t)(m0 + r) * 256 + e0 + q * 4);
        *(float4*)&cbuf[r * 36 + q * 4] = v;
    }
    if (tid < 96) wcb[tid] = wcp[(tid >> 5) * 256 + e0 + (tid & 31)];
    __syncthreads();

    int g = lane >> 2, t4 = lane & 3;
    #pragma unroll
    for (int mi = 0; mi < 2; mi++) {
        #pragma unroll
        for (int ni = 0; ni < 8; ni++) {
            int cloc = warp_n * 64 + ni * 8 + t4 * 2;
            float bias0 = __ldg(&g_bias[n0 + cloc]);
            float bias1 = __ldg(&g_bias[n0 + cloc + 1]);
            int eloc = warp_n * 16 + ni * 2 + (t4 >> 1);
            float wc0 = wcb[eloc], wc1 = wcb[32 + eloc], wc2 = wcb[64 + eloc];
            #pragma unroll
            for (int half = 0; half < 2; half++) {
                int row_loc = warp_m * 32 + mi * 16 + half * 8 + g;
                float v0 = acc[mi][ni][half * 2 + 0] + bias0;
                float v1 = acc[mi][ni][half * 2 + 1] + bias1;
                float p0 = __shfl_xor_sync(0xffffffffu, v0, 1);
                float p1 = __shfl_xor_sync(0xffffffffu, v1, 1);
                float pi, pf, pc, po;
                if ((t4 & 1) == 0) { pi = v0; pf = v1; pc = p0; po = p1; }
                else               { pi = p0; pf = p1; pc = v0; po = v1; }
                float cv = cbuf[row_loc * 36 + eloc];
                float I = fsigmoid(pi + wc0 * cv);
                float F = fsigmoid(pf + wc1 * cv);
                float T = ftanh(pc);
                float Cn = F * cv + I * T;
                float O = fsigmoid(po + wc2 * Cn);
                float Hn = O * ftanh(Cn);
                int so = row_loc * 36 + eloc;
                oO[so] = O; oH[so] = Hn; oC[so] = Cn;
            }
        }
    }
    __syncthreads();

    for (int i = tid; i < 128 * 8; i += 256) {
        int r = i >> 3, q = i & 7;
        int gr = m0 + r;
        if (gr < NN) {
            size_t go = (size_t)gr * 256 + e0 + q * 4;
            *(float4*)(out + go)                        = *(float4*)&oO[r * 36 + q * 4];
            *(float4*)(out + (size_t)NN * 256 + go)     = *(float4*)&oH[r * 36 + q * 4];
            *(float4*)(out + (size_t)2 * NN * 256 + go) = *(float4*)&oC[r * 36 + q * 4];
        }
    }
}

// ---------------- launch ----------------
extern "C" void kernel_launch(void* const* d_in, const int* in_sizes, int n_in,
                              void* d_out, int out_size) {
    const float* X    = (const float*)d_in[0];
    const void*  ei   = d_in[1];
    const float* h    = (const float*)d_in[2];
    const float* c    = (const float*)d_in[3];
    const float* Wx_l = (const float*)d_in[4];
    const float* bx_l = (const float*)d_in[5];
    const float* Wx_r = (const float*)d_in[6];
    const float* Wh_l = (const float*)d_in[7];
    const float* bh_l = (const float*)d_in[8];
    const float* Wh_r = (const float*)d_in[9];
    const float* wc   = (const float*)d_in[10];
    const float* b    = (const float*)d_in[11];
    float* out = (float*)d_out;

    static int smem_set = 0;
    if (!smem_set) {
        cudaFuncSetAttribute(k_mma, cudaFuncAttributeMaxDynamicSharedMemorySize, DYN_SMEM);
        smem_set = 1;
    }

    k_detect<<<1, 1>>>((const unsigned*)ei);
    k_convert<<<(EE + 255) / 256, 256>>>(ei);
    k_hist<<<(EE + 255) / 256, 256>>>();
    k_scan<<<1, 1024>>>();
    k_scatter<<<(EE + 255) / 256, 256>>>();
    k_agg<<<NN, 128>>>(X, h);
    k_packWt<<<(1024 * 1024 + 255) / 256, 256>>>(Wx_l, Wx_r, Wh_l, Wh_r, bx_l, bh_l, b);
    k_mma<<<dim3(8, 79), 256, DYN_SMEM>>>(c, wc, out);
}

// round 6
// speedup vs baseline: 1.0019x; 1.0019x over previous
#include <cuda_runtime.h>
#include <cuda_bf16.h>
#include <math.h>
#include <stdint.h>

#define NN 10000
#define EE 320000

// ---------------- scratch (static device globals; no allocation) ----------------
__device__ int   g_is64;
__device__ int   g_srcE[EE];
__device__ int   g_dstE[EE];
__device__ int   g_srcSorted[EE];
__device__ int   g_degi[NN];
__device__ int   g_cnt[NN];
__device__ int   g_off[NN + 1];
__device__ __nv_bfloat16 g_Ab[(size_t)NN * 2048];    // [hi(1024) | lo(1024)] per row
__device__ __nv_bfloat16 g_Wtb[(size_t)1024 * 2048]; // W^T: row j'(out col), [hi|lo]
__device__ float g_bias[1024];                       // bx_l + bh_l + b, in j' order

__device__ __forceinline__ uint32_t smem_u32(const void* p) {
    uint32_t a;
    asm("{ .reg .u64 t; cvta.to.shared.u64 t, %1; cvt.u32.u64 %0, t; }" : "=r"(a) : "l"(p));
    return a;
}

// ---------------- edge dtype detection (int32 vs int64) ----------------
__global__ void k_detect(const unsigned* __restrict__ w) {
    unsigned bad = 0;
    #pragma unroll
    for (int i = 0; i < 64; i++) bad |= w[2 * i + 1];
    g_is64 = (bad == 0) ? 1 : 0;
}

// convert edges + zero counters + build degree histogram, one pass
__global__ void k_convert(const void* __restrict__ ei) {
    int e = blockIdx.x * blockDim.x + threadIdx.x;
    if (e < NN) g_cnt[e] = 0;
    if (e >= EE) return;
    int src, dst;
    if (g_is64) {
        const long long* p = (const long long*)ei;
        src = (int)p[e]; dst = (int)p[EE + e];
    } else {
        const int* p = (const int*)ei;
        src = p[e]; dst = p[EE + e];
    }
    g_srcE[e] = src; g_dstE[e] = dst;
    atomicAdd(&g_degi[dst], 1);
}

__global__ void k_zero() {
    int i = blockIdx.x * blockDim.x + threadIdx.x;
    if (i < NN) g_degi[i] = 0;
}

// warp-shuffle scan: 1024 threads, 10 elems/thread
__global__ void k_scan() {
    __shared__ int warpsum[32];
    int t = threadIdx.x;
    int lane = t & 31, w = t >> 5;
    const int CH = 10;
    int base = t * CH;
    int v[CH];
    int loc = 0;
    #pragma unroll
    for (int i = 0; i < CH; i++) {
        int idx = base + i;
        v[i] = (idx < NN) ? g_degi[idx] : 0;
        loc += v[i];
    }
    int s = loc;
    #pragma unroll
    for (int off = 1; off < 32; off <<= 1) {
        int u = __shfl_up_sync(0xffffffffu, s, off);
        if (lane >= off) s += u;
    }
    if (lane == 31) warpsum[w] = s;
    __syncthreads();
    if (w == 0) {
        int ws = warpsum[lane];
        #pragma unroll
        for (int off = 1; off < 32; off <<= 1) {
            int u = __shfl_up_sync(0xffffffffu, ws, off);
            if (lane >= off) ws += u;
        }
        warpsum[lane] = ws;
    }
    __syncthreads();
    int wbase = (w > 0) ? warpsum[w - 1] : 0;
    int run = wbase + s - loc;  // exclusive prefix
    #pragma unroll
    for (int i = 0; i < CH; i++) {
        int idx = base + i;
        if (idx < NN) { g_off[idx] = run; run += v[i]; }
    }
    if (t == 1023) g_off[NN] = run;
}

__global__ void k_scatter() {
    int e = blockIdx.x * blockDim.x + threadIdx.x;
    if (e >= EE) return;
    int d = g_dstE[e];
    int pos = g_off[d] + atomicAdd(&g_cnt[d], 1);
    g_srcSorted[pos] = g_srcE[e];
}

// ---------------- aggregation + split-bf16 A packing ----------------
__device__ __forceinline__ void split_store(__nv_bfloat16* p, size_t hi_idx, float v) {
    __nv_bfloat16 hi = __float2bfloat16(v);
    float r = v - __bfloat162float(hi);
    p[hi_idx] = hi;
    p[hi_idx + 1024] = __float2bfloat16(r);
}

// 128 threads: t<64 -> X float4-chunk t ; t>=64 -> h float4-chunk t-64
__global__ __launch_bounds__(128) void k_agg(const float* __restrict__ X,
                                             const float* __restrict__ h) {
    __shared__ int sidx[128];
    int n = blockIdx.x, t = threadIdx.x;
    int s0 = g_off[n], s1 = g_off[n + 1];
    const float* basep = (t < 64) ? X : h;
    int q = (t & 63) * 4;
    float ax = 0.f, ay = 0.f, az = 0.f, aw = 0.f;
    for (int bs = s0; bs < s1; bs += 128) {
        int cnt = min(128, s1 - bs);
        if (t < cnt) sidx[t] = g_srcSorted[bs + t];
        __syncthreads();
        int j = 0;
        for (; j + 4 <= cnt; j += 4) {
            float4 a = *(const float4*)(basep + (size_t)sidx[j]     * 256 + q);
            float4 b2 = *(const float4*)(basep + (size_t)sidx[j + 1] * 256 + q);
            float4 c2 = *(const float4*)(basep + (size_t)sidx[j + 2] * 256 + q);
            float4 d2 = *(const float4*)(basep + (size_t)sidx[j + 3] * 256 + q);
            ax += a.x + b2.x + c2.x + d2.x;
            ay += a.y + b2.y + c2.y + d2.y;
            az += a.z + b2.z + c2.z + d2.z;
            aw += a.w + b2.w + c2.w + d2.w;
        }
        for (; j < cnt; j++) {
            float4 a = *(const float4*)(basep + (size_t)sidx[j] * 256 + q);
            ax += a.x; ay += a.y; az += a.z; aw += a.w;
        }
        __syncthreads();
    }
    int deg = s1 - s0;
    float inv = 1.f / (float)(deg > 0 ? deg : 1);
    float4 self = *(const float4*)(basep + (size_t)n * 256 + q);
    size_t o = (size_t)n * 2048;
    int seg = (t < 64) ? 0 : 512;  // aggX cols 0-255, X 256-511, aggH 512-767, h 768-1023
    split_store(g_Ab, o + seg + q + 0, ax * inv);
    split_store(g_Ab, o + seg + q + 1, ay * inv);
    split_store(g_Ab, o + seg + q + 2, az * inv);
    split_store(g_Ab, o + seg + q + 3, aw * inv);
    split_store(g_Ab, o + seg + 256 + q + 0, self.x);
    split_store(g_Ab, o + seg + 256 + q + 1, self.y);
    split_store(g_Ab, o + seg + 256 + q + 2, self.z);
    split_store(g_Ab, o + seg + 256 + q + 3, self.w);
}

// ---------------- weight packing: col order j' = 4*e + gate ----------------
__global__ void k_packWt(const float* __restrict__ Wx_l, const float* __restrict__ Wx_r,
                         const float* __restrict__ Wh_l, const float* __restrict__ Wh_r,
                         const float* __restrict__ bx_l, const float* __restrict__ bh_l,
                         const float* __restrict__ bb) {
    int idx = blockIdx.x * blockDim.x + threadIdx.x;
    if (idx >= 1024 * 1024) return;
    int d = idx & 1023;      // K row
    int jp = idx >> 10;      // output col (interleaved)
    int e = jp >> 2, k = jp & 3;
    int seg = d >> 8, dd = d & 255;
    const float* src = (seg == 0) ? Wx_l : (seg == 1) ? Wx_r : (seg == 2) ? Wh_l : Wh_r;
    float w = src[k * 65536 + dd * 256 + e];
    split_store(g_Wtb, (size_t)jp * 2048 + d, w);
    if (d == 0)
        g_bias[jp] = bx_l[k * 256 + e] + bh_l[k * 256 + e] + bb[k * 256 + e];
}

// ---------------- mma.sync bf16 GEMM + fused gates ----------------
#define BM 128
#define BN 128
#define NITER 48   // 3 segments * 1024 / 64
#define TILE_B 16384
#define STAGE_B (2 * TILE_B)
#define DYN_SMEM (3 * STAGE_B)

#define LDSM_X4(r0, r1, r2, r3, addr) \
    asm volatile("ldmatrix.sync.aligned.m8n8.x4.shared.b16 {%0,%1,%2,%3}, [%4];" \
                 : "=r"(r0), "=r"(r1), "=r"(r2), "=r"(r3) : "r"(addr))

#define MMA16816(d, a0, a1, a2, a3, b0, b1) \
    asm volatile("mma.sync.aligned.m16n8k16.row.col.f32.bf16.bf16.f32 " \
                 "{%0,%1,%2,%3}, {%4,%5,%6,%7}, {%8,%9}, {%0,%1,%2,%3};" \
                 : "+f"((d)[0]), "+f"((d)[1]), "+f"((d)[2]), "+f"((d)[3]) \
                 : "r"(a0), "r"(a1), "r"(a2), "r"(a3), "r"(b0), "r"(b1))

__device__ __forceinline__ void issue_tile(uint32_t sA, uint32_t sB, int m0, int n0,
                                           int it, int tid) {
    int k0 = it * 64;
    int seg = k0 >> 10, kk = k0 & 1023;
    int acol = kk + (seg == 2 ? 1024 : 0);
    int bcol = kk + (seg == 1 ? 1024 : 0);
    #pragma unroll
    for (int i = 0; i < 4; i++) {
        int ch = tid + i * 256;
        int row = ch >> 3, c = ch & 7;
        uint32_t so = row * 128 + ((c ^ (row & 7)) << 4);
        const __nv_bfloat16* ga = g_Ab + (size_t)(m0 + row) * 2048 + acol + c * 8;
        unsigned sz = (m0 + row < NN) ? 16u : 0u;
        asm volatile("cp.async.cg.shared.global [%0], [%1], 16, %2;"
                     :: "r"(sA + so), "l"(ga), "r"(sz));
        const __nv_bfloat16* gb = g_Wtb + (size_t)(n0 + row) * 2048 + bcol + c * 8;
        asm volatile("cp.async.cg.shared.global [%0], [%1], 16;"
                     :: "r"(sB + so), "l"(gb));
    }
}

__device__ __forceinline__ float fsigmoid(float x) { return 1.f / (1.f + __expf(-x)); }
__device__ __forceinline__ float ftanh(float x) {
    float e = __expf(-2.f * x);
    return (1.f - e) / (1.f + e);
}

__global__ __launch_bounds__(256, 2) void k_mma(const float* __restrict__ cptr,
                                                const float* __restrict__ wcp,
                                                float* __restrict__ out) {
    extern __shared__ char smem[];
    uint32_t sb = smem_u32(smem);
    int tid = threadIdx.x;
    int lane = tid & 31, wid = tid >> 5;
    int warp_m = wid & 3, warp_n = wid >> 2;
    int m0 = blockIdx.y * BM, n0 = blockIdx.x * BN;
    int e0 = n0 >> 2;  // 32 features per col tile

    float acc[2][8][4];
    #pragma unroll
    for (int i = 0; i < 2; i++)
        #pragma unroll
        for (int j = 0; j < 8; j++)
            #pragma unroll
            for (int r = 0; r < 4; r++) acc[i][j][r] = 0.f;

    uint32_t sA[3], sB[3];
    #pragma unroll
    for (int s = 0; s < 3; s++) { sA[s] = sb + s * STAGE_B; sB[s] = sA[s] + TILE_B; }

    issue_tile(sA[0], sB[0], m0, n0, 0, tid);
    asm volatile("cp.async.commit_group;" ::: "memory");
    issue_tile(sA[1], sB[1], m0, n0, 1, tid);
    asm volatile("cp.async.commit_group;" ::: "memory");

    // ldmatrix address invariants
    int rowA[2], rowA7[2];
    #pragma unroll
    for (int mi = 0; mi < 2; mi++) {
        int r = warp_m * 32 + mi * 16 + (lane & 15);
        rowA[mi] = r * 128;
        rowA7[mi] = r & 7;
    }
    int achk = lane >> 4;
    int local = lane & 7, quad = lane >> 3;
    int bchk = quad & 1;
    int rowB[4], rowB7[4];
    #pragma unroll
    for (int np = 0; np < 4; np++) {
        int r = warp_n * 64 + np * 16 + ((quad >> 1) << 3) + local;
        rowB[np] = r * 128;
        rowB7[np] = r & 7;
    }

    for (int it = 0; it < NITER; it++) {
        asm volatile("cp.async.wait_group 1;" ::: "memory");
        __syncthreads();
        if (it + 2 < NITER)
            issue_tile(sA[(it + 2) % 3], sB[(it + 2) % 3], m0, n0, it + 2, tid);
        asm volatile("cp.async.commit_group;" ::: "memory");
        int s = it % 3;
        uint32_t Ab = sA[s], Bb = sB[s];
        #pragma unroll
        for (int ks = 0; ks < 4; ks++) {
            uint32_t a[2][4];
            #pragma unroll
            for (int mi = 0; mi < 2; mi++) {
                uint32_t ad = Ab + rowA[mi] + ((((ks * 2 + achk)) ^ rowA7[mi]) << 4);
                LDSM_X4(a[mi][0], a[mi][1], a[mi][2], a[mi][3], ad);
            }
            #pragma unroll
            for (int np = 0; np < 4; np++) {
                uint32_t bd = Bb + rowB[np] + ((((ks * 2 + bchk)) ^ rowB7[np]) << 4);
                uint32_t t0, t1, t2, t3;
                LDSM_X4(t0, t1, t2, t3, bd);
                MMA16816(acc[0][np * 2],     a[0][0], a[0][1], a[0][2], a[0][3], t0, t1);
                MMA16816(acc[1][np * 2],     a[1][0], a[1][1], a[1][2], a[1][3], t0, t1);
                MMA16816(acc[0][np * 2 + 1], a[0][0], a[0][1], a[0][2], a[0][3], t2, t3);
                MMA16816(acc[1][np * 2 + 1], a[1][0], a[1][1], a[1][2], a[1][3], t2, t3);
            }
        }
    }
    __syncthreads();  // done with pipeline smem

    // -------- fused gate epilogue --------
    // smem reuse: cbuf[128][36], oO/oH/oC[128][36], wcb[3][32]
    float* cbuf = (float*)smem;
    float* oO = (float*)(smem + 18432);
    float* oH = (float*)(smem + 36864);
    float* oC = (float*)(smem + 55296);
    float* wcb = (float*)(smem + 73728);

    for (int i = tid; i < 128 * 8; i += 256) {
        int r = i >> 3, q = i & 7;
        float4 v = make_float4(0.f, 0.f, 0.f, 0.f);
        if (m0 + r < NN) v = *(const float4*)(cptr + (size_t)(m0 + r) * 256 + e0 + q * 4);
        *(float4*)&cbuf[r * 36 + q * 4] = v;
    }
    if (tid < 96) wcb[tid] = wcp[(tid >> 5) * 256 + e0 + (tid & 31)];
    __syncthreads();

    int g = lane >> 2, t4 = lane & 3;
    #pragma unroll
    for (int mi = 0; mi < 2; mi++) {
        #pragma unroll
        for (int ni = 0; ni < 8; ni++) {
            int cloc = warp_n * 64 + ni * 8 + t4 * 2;
            float bias0 = __ldg(&g_bias[n0 + cloc]);
            float bias1 = __ldg(&g_bias[n0 + cloc + 1]);
            int eloc = warp_n * 16 + ni * 2 + (t4 >> 1);
            float wc0 = wcb[eloc], wc1 = wcb[32 + eloc], wc2 = wcb[64 + eloc];
            #pragma unroll
            for (int half = 0; half < 2; half++) {
                int row_loc = warp_m * 32 + mi * 16 + half * 8 + g;
                float v0 = acc[mi][ni][half * 2 + 0] + bias0;
                float v1 = acc[mi][ni][half * 2 + 1] + bias1;
                float p0 = __shfl_xor_sync(0xffffffffu, v0, 1);
                float p1 = __shfl_xor_sync(0xffffffffu, v1, 1);
                float pi, pf, pc, po;
                if ((t4 & 1) == 0) { pi = v0; pf = v1; pc = p0; po = p1; }
                else               { pi = p0; pf = p1; pc = v0; po = v1; }
                float cv = cbuf[row_loc * 36 + eloc];
                float I = fsigmoid(pi + wc0 * cv);
                float F = fsigmoid(pf + wc1 * cv);
                float T = ftanh(pc);
                float Cn = F * cv + I * T;
                float O = fsigmoid(po + wc2 * Cn);
                float Hn = O * ftanh(Cn);
                int so = row_loc * 36 + eloc;
                oO[so] = O; oH[so] = Hn; oC[so] = Cn;
            }
        }
    }
    __syncthreads();

    for (int i = tid; i < 128 * 8; i += 256) {
        int r = i >> 3, q = i & 7;
        int gr = m0 + r;
        if (gr < NN) {
            size_t go = (size_t)gr * 256 + e0 + q * 4;
            *(float4*)(out + go)                        = *(float4*)&oO[r * 36 + q * 4];
            *(float4*)(out + (size_t)NN * 256 + go)     = *(float4*)&oH[r * 36 + q * 4];
            *(float4*)(out + (size_t)2 * NN * 256 + go) = *(float4*)&oC[r * 36 + q * 4];
        }
    }
}

// ---------------- launch ----------------
extern "C" void kernel_launch(void* const* d_in, const int* in_sizes, int n_in,
                              void* d_out, int out_size) {
    const float* X    = (const float*)d_in[0];
    const void*  ei   = d_in[1];
    const float* h    = (const float*)d_in[2];
    const float* c    = (const float*)d_in[3];
    const float* Wx_l = (const float*)d_in[4];
    const float* bx_l = (const float*)d_in[5];
    const float* Wx_r = (const float*)d_in[6];
    const float* Wh_l = (const float*)d_in[7];
    const float* bh_l = (const float*)d_in[8];
    const float* Wh_r = (const float*)d_in[9];
    const float* wc   = (const float*)d_in[10];
    const float* b    = (const float*)d_in[11];
    float* out = (float*)d_out;

    static int smem_set = 0;
    if (!smem_set) {
        cudaFuncSetAttribute(k_mma, cudaFuncAttributeMaxDynamicSharedMemorySize, DYN_SMEM);
        smem_set = 1;
    }

    k_detect<<<1, 1>>>((const unsigned*)ei);
    k_zero<<<(NN + 255) / 256, 256>>>();
    k_convert<<<(EE + 255) / 256, 256>>>(ei);
    k_scan<<<1, 1024>>>();
    k_scatter<<<(EE + 255) / 256, 256>>>();
    k_agg<<<NN, 128>>>(X, h);
    k_packWt<<<(1024 * 1024 + 255) / 256, 256>>>(Wx_l, Wx_r, Wh_l, Wh_r, bx_l, bh_l, b);
    k_mma<<<dim3(8, 79), 256, DYN_SMEM>>>(c, wc, out);
}

// round 7
// speedup vs baseline: 1.7224x; 1.7191x over previous
#include <cuda_runtime.h>
#include <cuda_fp16.h>
#include <math.h>
#include <stdint.h>

#define NN 10000
#define EE 320000

// ---------------- scratch (static device globals; no allocation) ----------------
__device__ int   g_is64;
__device__ int   g_srcE[EE];
__device__ int   g_dstE[EE];
__device__ int   g_srcSorted[EE];
__device__ int   g_degi[NN];
__device__ int   g_cnt[NN];
__device__ int   g_off[NN + 1];
__device__ __half g_Ab[(size_t)NN * 1024];    // [aggX | X | aggH | h] fp16
__device__ __half g_Wtb[(size_t)1024 * 1024]; // W^T: row j'(out col), K contiguous
__device__ float g_bias[1024];                // bx_l + bh_l + b, in j' order

__device__ __forceinline__ uint32_t smem_u32(const void* p) {
    uint32_t a;
    asm("{ .reg .u64 t; cvta.to.shared.u64 t, %1; cvt.u32.u64 %0, t; }" : "=r"(a) : "l"(p));
    return a;
}

// ---------------- edge dtype detection (int32 vs int64) ----------------
__global__ void k_detect(const unsigned* __restrict__ w) {
    unsigned bad = 0;
    #pragma unroll
    for (int i = 0; i < 64; i++) bad |= w[2 * i + 1];
    g_is64 = (bad == 0) ? 1 : 0;
}

// convert edges + zero cnt + build degree histogram, one pass
__global__ void k_convert(const void* __restrict__ ei) {
    int e = blockIdx.x * blockDim.x + threadIdx.x;
    if (e < NN) g_cnt[e] = 0;
    if (e >= EE) return;
    int src, dst;
    if (g_is64) {
        const long long* p = (const long long*)ei;
        src = (int)p[e]; dst = (int)p[EE + e];
    } else {
        const int* p = (const int*)ei;
        src = p[e]; dst = p[EE + e];
    }
    g_srcE[e] = src; g_dstE[e] = dst;
    atomicAdd(&g_degi[dst], 1);
}

__global__ void k_zero() {
    int i = blockIdx.x * blockDim.x + threadIdx.x;
    if (i < NN) g_degi[i] = 0;
}

// warp-shuffle scan: 1024 threads, 10 elems/thread
__global__ void k_scan() {
    __shared__ int warpsum[32];
    int t = threadIdx.x;
    int lane = t & 31, w = t >> 5;
    const int CH = 10;
    int base = t * CH;
    int v[CH];
    int loc = 0;
    #pragma unroll
    for (int i = 0; i < CH; i++) {
        int idx = base + i;
        v[i] = (idx < NN) ? g_degi[idx] : 0;
        loc += v[i];
    }
    int s = loc;
    #pragma unroll
    for (int off = 1; off < 32; off <<= 1) {
        int u = __shfl_up_sync(0xffffffffu, s, off);
        if (lane >= off) s += u;
    }
    if (lane == 31) warpsum[w] = s;
    __syncthreads();
    if (w == 0) {
        int ws = warpsum[lane];
        #pragma unroll
        for (int off = 1; off < 32; off <<= 1) {
            int u = __shfl_up_sync(0xffffffffu, ws, off);
            if (lane >= off) ws += u;
        }
        warpsum[lane] = ws;
    }
    __syncthreads();
    int wbase = (w > 0) ? warpsum[w - 1] : 0;
    int run = wbase + s - loc;  // exclusive prefix
    #pragma unroll
    for (int i = 0; i < CH; i++) {
        int idx = base + i;
        if (idx < NN) { g_off[idx] = run; run += v[i]; }
    }
    if (t == 1023) g_off[NN] = run;
}

__global__ void k_scatter() {
    int e = blockIdx.x * blockDim.x + threadIdx.x;
    if (e >= EE) return;
    int d = g_dstE[e];
    int pos = g_off[d] + atomicAdd(&g_cnt[d], 1);
    g_srcSorted[pos] = g_srcE[e];
}

// ---------------- aggregation + fp16 A packing ----------------
// 128 threads: t<64 -> X float4-chunk t ; t>=64 -> h float4-chunk t-64
__global__ __launch_bounds__(128) void k_agg(const float* __restrict__ X,
                                             const float* __restrict__ h) {
    __shared__ int sidx[128];
    int n = blockIdx.x, t = threadIdx.x;
    int s0 = g_off[n], s1 = g_off[n + 1];
    const float* basep = (t < 64) ? X : h;
    int q = (t & 63) * 4;
    float ax = 0.f, ay = 0.f, az = 0.f, aw = 0.f;
    for (int bs = s0; bs < s1; bs += 128) {
        int cnt = min(128, s1 - bs);
        if (t < cnt) sidx[t] = g_srcSorted[bs + t];
        __syncthreads();
        int j = 0;
        for (; j + 4 <= cnt; j += 4) {
            float4 a = *(const float4*)(basep + (size_t)sidx[j]     * 256 + q);
            float4 b2 = *(const float4*)(basep + (size_t)sidx[j + 1] * 256 + q);
            float4 c2 = *(const float4*)(basep + (size_t)sidx[j + 2] * 256 + q);
            float4 d2 = *(const float4*)(basep + (size_t)sidx[j + 3] * 256 + q);
            ax += a.x + b2.x + c2.x + d2.x;
            ay += a.y + b2.y + c2.y + d2.y;
            az += a.z + b2.z + c2.z + d2.z;
            aw += a.w + b2.w + c2.w + d2.w;
        }
        for (; j < cnt; j++) {
            float4 a = *(const float4*)(basep + (size_t)sidx[j] * 256 + q);
            ax += a.x; ay += a.y; az += a.z; aw += a.w;
        }
        __syncthreads();
    }
    int deg = s1 - s0;
    float inv = 1.f / (float)(deg > 0 ? deg : 1);
    float4 self = *(const float4*)(basep + (size_t)n * 256 + q);
    size_t o = (size_t)n * 1024;
    int seg = (t < 64) ? 0 : 512;  // aggX 0-255, X 256-511, aggH 512-767, h 768-1023
    __half2* d0 = (__half2*)&g_Ab[o + seg + q];
    d0[0] = __floats2half2_rn(ax * inv, ay * inv);
    d0[1] = __floats2half2_rn(az * inv, aw * inv);
    __half2* d1 = (__half2*)&g_Ab[o + seg + 256 + q];
    d1[0] = __floats2half2_rn(self.x, self.y);
    d1[1] = __floats2half2_rn(self.z, self.w);
}

// ---------------- weight packing: col order j' = 4*e + gate ----------------
__global__ void k_packWt(const float* __restrict__ Wx_l, const float* __restrict__ Wx_r,
                         const float* __restrict__ Wh_l, const float* __restrict__ Wh_r,
                         const float* __restrict__ bx_l, const float* __restrict__ bh_l,
                         const float* __restrict__ bb) {
    int idx = blockIdx.x * blockDim.x + threadIdx.x;
    if (idx >= 1024 * 1024) return;
    int d = idx & 1023;      // K row
    int jp = idx >> 10;      // output col (interleaved)
    int e = jp >> 2, k = jp & 3;
    int seg = d >> 8, dd = d & 255;
    const float* src = (seg == 0) ? Wx_l : (seg == 1) ? Wx_r : (seg == 2) ? Wh_l : Wh_r;
    float w = src[k * 65536 + dd * 256 + e];
    g_Wtb[(size_t)jp * 1024 + d] = __float2half_rn(w);
    if (d == 0)
        g_bias[jp] = bx_l[k * 256 + e] + bh_l[k * 256 + e] + bb[k * 256 + e];
}

// ---------------- mma.sync fp16 GEMM (single pass, K=1024) + fused gates ----------------
#define BM 128
#define BN 128
#define NITER 16   // 1024 / 64
#define TILE_B 16384
#define STAGE_B (2 * TILE_B)
#define DYN_SMEM (3 * STAGE_B)

#define LDSM_X4(r0, r1, r2, r3, addr) \
    asm volatile("ldmatrix.sync.aligned.m8n8.x4.shared.b16 {%0,%1,%2,%3}, [%4];" \
                 : "=r"(r0), "=r"(r1), "=r"(r2), "=r"(r3) : "r"(addr))

#define MMA16816(d, a0, a1, a2, a3, b0, b1) \
    asm volatile("mma.sync.aligned.m16n8k16.row.col.f32.f16.f16.f32 " \
                 "{%0,%1,%2,%3}, {%4,%5,%6,%7}, {%8,%9}, {%0,%1,%2,%3};" \
                 : "+f"((d)[0]), "+f"((d)[1]), "+f"((d)[2]), "+f"((d)[3]) \
                 : "r"(a0), "r"(a1), "r"(a2), "r"(a3), "r"(b0), "r"(b1))

__device__ __forceinline__ void issue_tile(uint32_t sA, uint32_t sB, int m0, int n0,
                                           int it, int tid) {
    int kk = it * 64;
    #pragma unroll
    for (int i = 0; i < 4; i++) {
        int ch = tid + i * 256;
        int row = ch >> 3, c = ch & 7;
        uint32_t so = row * 128 + ((c ^ (row & 7)) << 4);
        const __half* ga = g_Ab + (size_t)(m0 + row) * 1024 + kk + c * 8;
        unsigned sz = (m0 + row < NN) ? 16u : 0u;
        asm volatile("cp.async.cg.shared.global [%0], [%1], 16, %2;"
                     :: "r"(sA + so), "l"(ga), "r"(sz));
        const __half* gb = g_Wtb + (size_t)(n0 + row) * 1024 + kk + c * 8;
        asm volatile("cp.async.cg.shared.global [%0], [%1], 16;"
                     :: "r"(sB + so), "l"(gb));
    }
}

__device__ __forceinline__ float fsigmoid(float x) { return 1.f / (1.f + __expf(-x)); }
__device__ __forceinline__ float ftanh(float x) {
    float e = __expf(-2.f * x);
    return (1.f - e) / (1.f + e);
}

__global__ __launch_bounds__(256, 2) void k_mma(const float* __restrict__ cptr,
                                                const float* __restrict__ wcp,
                                                float* __restrict__ out) {
    extern __shared__ char smem[];
    uint32_t sb = smem_u32(smem);
    int tid = threadIdx.x;
    int lane = tid & 31, wid = tid >> 5;
    int warp_m = wid & 3, warp_n = wid >> 2;
    int m0 = blockIdx.y * BM, n0 = blockIdx.x * BN;
    int e0 = n0 >> 2;  // 32 features per col tile

    float acc[2][8][4];
    #pragma unroll
    for (int i = 0; i < 2; i++)
        #pragma unroll
        for (int j = 0; j < 8; j++)
            #pragma unroll
            for (int r = 0; r < 4; r++) acc[i][j][r] = 0.f;

    uint32_t sA[3], sB[3];
    #pragma unroll
    for (int s = 0; s < 3; s++) { sA[s] = sb + s * STAGE_B; sB[s] = sA[s] + TILE_B; }

    issue_tile(sA[0], sB[0], m0, n0, 0, tid);
    asm volatile("cp.async.commit_group;" ::: "memory");
    issue_tile(sA[1], sB[1], m0, n0, 1, tid);
    asm volatile("cp.async.commit_group;" ::: "memory");

    // ldmatrix address invariants
    int rowA[2], rowA7[2];
    #pragma unroll
    for (int mi = 0; mi < 2; mi++) {
        int r = warp_m * 32 + mi * 16 + (lane & 15);
        rowA[mi] = r * 128;
        rowA7[mi] = r & 7;
    }
    int achk = lane >> 4;
    int local = lane & 7, quad = lane >> 3;
    int bchk = quad & 1;
    int rowB[4], rowB7[4];
    #pragma unroll
    for (int np = 0; np < 4; np++) {
        int r = warp_n * 64 + np * 16 + ((quad >> 1) << 3) + local;
        rowB[np] = r * 128;
        rowB7[np] = r & 7;
    }

    for (int it = 0; it < NITER; it++) {
        asm volatile("cp.async.wait_group 1;" ::: "memory");
        __syncthreads();
        if (it + 2 < NITER)
            issue_tile(sA[(it + 2) % 3], sB[(it + 2) % 3], m0, n0, it + 2, tid);
        asm volatile("cp.async.commit_group;" ::: "memory");
        int s = it % 3;
        uint32_t Ab = sA[s], Bb = sB[s];
        #pragma unroll
        for (int ks = 0; ks < 4; ks++) {
            uint32_t a[2][4];
            #pragma unroll
            for (int mi = 0; mi < 2; mi++) {
                uint32_t ad = Ab + rowA[mi] + ((((ks * 2 + achk)) ^ rowA7[mi]) << 4);
                LDSM_X4(a[mi][0], a[mi][1], a[mi][2], a[mi][3], ad);
            }
            #pragma unroll
            for (int np = 0; np < 4; np++) {
                uint32_t bd = Bb + rowB[np] + ((((ks * 2 + bchk)) ^ rowB7[np]) << 4);
                uint32_t t0, t1, t2, t3;
                LDSM_X4(t0, t1, t2, t3, bd);
                MMA16816(acc[0][np * 2],     a[0][0], a[0][1], a[0][2], a[0][3], t0, t1);
                MMA16816(acc[1][np * 2],     a[1][0], a[1][1], a[1][2], a[1][3], t0, t1);
                MMA16816(acc[0][np * 2 + 1], a[0][0], a[0][1], a[0][2], a[0][3], t2, t3);
                MMA16816(acc[1][np * 2 + 1], a[1][0], a[1][1], a[1][2], a[1][3], t2, t3);
            }
        }
    }
    __syncthreads();  // done with pipeline smem

    // -------- fused gate epilogue --------
    // smem reuse: cbuf[128][36], oO/oH/oC[128][36], wcb[3][32]
    float* cbuf = (float*)smem;
    float* oO = (float*)(smem + 18432);
    float* oH = (float*)(smem + 36864);
    float* oC = (float*)(smem + 55296);
    float* wcb = (float*)(smem + 73728);

    for (int i = tid; i < 128 * 8; i += 256) {
        int r = i >> 3, q = i & 7;
        float4 v = make_float4(0.f, 0.f, 0.f, 0.f);
        if (m0 + r < NN) v = *(const float4*)(cptr + (size_t)(m0 + r) * 256 + e0 + q * 4);
        *(float4*)&cbuf[r * 36 + q * 4] = v;
    }
    if (tid < 96) wcb[tid] = wcp[(tid >> 5) * 256 + e0 + (tid & 31)];
    __syncthreads();

    int g = lane >> 2, t4 = lane & 3;
    #pragma unroll
    for (int mi = 0; mi < 2; mi++) {
        #pragma unroll
        for (int ni = 0; ni < 8; ni++) {
            int cloc = warp_n * 64 + ni * 8 + t4 * 2;
            float bias0 = __ldg(&g_bias[n0 + cloc]);
            float bias1 = __ldg(&g_bias[n0 + cloc + 1]);
            int eloc = warp_n * 16 + ni * 2 + (t4 >> 1);
            float wc0 = wcb[eloc], wc1 = wcb[32 + eloc], wc2 = wcb[64 + eloc];
            #pragma unroll
            for (int half = 0; half < 2; half++) {
                int row_loc = warp_m * 32 + mi * 16 + half * 8 + g;
                float v0 = acc[mi][ni][half * 2 + 0] + bias0;
                float v1 = acc[mi][ni][half * 2 + 1] + bias1;
                float p0 = __shfl_xor_sync(0xffffffffu, v0, 1);
                float p1 = __shfl_xor_sync(0xffffffffu, v1, 1);
                float pi, pf, pc, po;
                if ((t4 & 1) == 0) { pi = v0; pf = v1; pc = p0; po = p1; }
                else               { pi = p0; pf = p1; pc = v0; po = v1; }
                float cv = cbuf[row_loc * 36 + eloc];
                float I = fsigmoid(pi + wc0 * cv);
                float F = fsigmoid(pf + wc1 * cv);
                float T = ftanh(pc);
                float Cn = F * cv + I * T;
                float O = fsigmoid(po + wc2 * Cn);
                float Hn = O * ftanh(Cn);
                int so = row_loc * 36 + eloc;
                oO[so] = O; oH[so] = Hn; oC[so] = Cn;
            }
        }
    }
    __syncthreads();

    for (int i = tid; i < 128 * 8; i += 256) {
        int r = i >> 3, q = i & 7;
        int gr = m0 + r;
        if (gr < NN) {
            size_t go = (size_t)gr * 256 + e0 + q * 4;
            *(float4*)(out + go)                        = *(float4*)&oO[r * 36 + q * 4];
            *(float4*)(out + (size_t)NN * 256 + go)     = *(float4*)&oH[r * 36 + q * 4];
            *(float4*)(out + (size_t)2 * NN * 256 + go) = *(float4*)&oC[r * 36 + q * 4];
        }
    }
}

// ---------------- launch ----------------
extern "C" void kernel_launch(void* const* d_in, const int* in_sizes, int n_in,
                              void* d_out, int out_size) {
    const float* X    = (const float*)d_in[0];
    const void*  ei   = d_in[1];
    const float* h    = (const float*)d_in[2];
    const float* c    = (const float*)d_in[3];
    const float* Wx_l = (const float*)d_in[4];
    const float* bx_l = (const float*)d_in[5];
    const float* Wx_r = (const float*)d_in[6];
    const float* Wh_l = (const float*)d_in[7];
    const float* bh_l = (const float*)d_in[8];
    const float* Wh_r = (const float*)d_in[9];
    const float* wc   = (const float*)d_in[10];
    const float* b    = (const float*)d_in[11];
    float* out = (float*)d_out;

    static int smem_set = 0;
    if (!smem_set) {
        cudaFuncSetAttribute(k_mma, cudaFuncAttributeMaxDynamicSharedMemorySize, DYN_SMEM);
        smem_set = 1;
    }

    k_detect<<<1, 1>>>((const unsigned*)ei);
    k_zero<<<(NN + 255) / 256, 256>>>();
    k_convert<<<(EE + 255) / 256, 256>>>(ei);
    k_scan<<<1, 1024>>>();
    k_scatter<<<(EE + 255) / 256, 256>>>();
    k_agg<<<NN, 128>>>(X, h);
    k_packWt<<<(1024 * 1024 + 255) / 256, 256>>>(Wx_l, Wx_r, Wh_l, Wh_r, bx_l, bh_l, b);
    k_mma<<<dim3(8, 79), 256, DYN_SMEM>>>(c, wc, out);
}

// round 8
// speedup vs baseline: 1.8008x; 1.0455x over previous
#include <cuda_runtime.h>
#include <cuda_fp16.h>
#include <math.h>
#include <stdint.h>

#define NN 10000
#define EE 320000

// ---------------- scratch (static device globals; no allocation) ----------------
__device__ int   g_is64;
__device__ int   g_srcE[EE];
__device__ int   g_dstE[EE];
__device__ int   g_srcSorted[EE];
__device__ int   g_degi[NN];
__device__ int   g_cnt[NN];
__device__ int   g_off[NN + 1];
__device__ __half g_X16[(size_t)NN * 256];
__device__ __half g_h16[(size_t)NN * 256];
__device__ __half g_Ab[(size_t)NN * 1024];    // [aggX | X | aggH | h] fp16
__device__ __half g_Wtb[(size_t)1024 * 1024]; // W^T: row j'(out col), K contiguous
__device__ float g_bias[1024];                // bx_l + bh_l + b, in j' order

__device__ __forceinline__ uint32_t smem_u32(const void* p) {
    uint32_t a;
    asm("{ .reg .u64 t; cvta.to.shared.u64 t, %1; cvt.u32.u64 %0, t; }" : "=r"(a) : "l"(p));
    return a;
}

// ---------------- init: zero counters + edge dtype detect ----------------
__global__ void k_init(const unsigned* __restrict__ w) {
    int i = blockIdx.x * blockDim.x + threadIdx.x;
    if (i < NN) { g_degi[i] = 0; g_cnt[i] = 0; }
    if (i == 0) {
        unsigned bad = 0;
        #pragma unroll
        for (int k = 0; k < 64; k++) bad |= w[2 * k + 1];
        g_is64 = (bad == 0) ? 1 : 0;
    }
}

// convert edges + build degree histogram, one pass
__global__ void k_convert(const void* __restrict__ ei) {
    int e = blockIdx.x * blockDim.x + threadIdx.x;
    if (e >= EE) return;
    int src, dst;
    if (g_is64) {
        const long long* p = (const long long*)ei;
        src = (int)p[e]; dst = (int)p[EE + e];
    } else {
        const int* p = (const int*)ei;
        src = p[e]; dst = p[EE + e];
    }
    g_srcE[e] = src; g_dstE[e] = dst;
    atomicAdd(&g_degi[dst], 1);
}

// warp-shuffle scan: 1024 threads, 10 elems/thread
__global__ void k_scan() {
    __shared__ int warpsum[32];
    int t = threadIdx.x;
    int lane = t & 31, w = t >> 5;
    const int CH = 10;
    int base = t * CH;
    int v[CH];
    int loc = 0;
    #pragma unroll
    for (int i = 0; i < CH; i++) {
        int idx = base + i;
        v[i] = (idx < NN) ? g_degi[idx] : 0;
        loc += v[i];
    }
    int s = loc;
    #pragma unroll
    for (int off = 1; off < 32; off <<= 1) {
        int u = __shfl_up_sync(0xffffffffu, s, off);
        if (lane >= off) s += u;
    }
    if (lane == 31) warpsum[w] = s;
    __syncthreads();
    if (w == 0) {
        int ws = warpsum[lane];
        #pragma unroll
        for (int off = 1; off < 32; off <<= 1) {
            int u = __shfl_up_sync(0xffffffffu, ws, off);
            if (lane >= off) ws += u;
        }
        warpsum[lane] = ws;
    }
    __syncthreads();
    int wbase = (w > 0) ? warpsum[w - 1] : 0;
    int run = wbase + s - loc;  // exclusive prefix
    #pragma unroll
    for (int i = 0; i < CH; i++) {
        int idx = base + i;
        if (idx < NN) { g_off[idx] = run; run += v[i]; }
    }
    if (t == 1023) g_off[NN] = run;
}

__global__ void k_scatter() {
    int e = blockIdx.x * blockDim.x + threadIdx.x;
    if (e >= EE) return;
    int d = g_dstE[e];
    int pos = g_off[d] + atomicAdd(&g_cnt[d], 1);
    g_srcSorted[pos] = g_srcE[e];
}

// ---------------- fp32 -> fp16 conversion of X and h ----------------
__global__ void k_tofp16(const float* __restrict__ X, const float* __restrict__ h) {
    int i = blockIdx.x * blockDim.x + threadIdx.x;  // 4 elems per thread
    if (i >= NN * 64) return;
    float4 vx = *(const float4*)(X + (size_t)i * 4);
    float4 vh = *(const float4*)(h + (size_t)i * 4);
    __half2* px = (__half2*)(g_X16 + (size_t)i * 4);
    px[0] = __floats2half2_rn(vx.x, vx.y);
    px[1] = __floats2half2_rn(vx.z, vx.w);
    __half2* ph = (__half2*)(g_h16 + (size_t)i * 4);
    ph[0] = __floats2half2_rn(vh.x, vh.y);
    ph[1] = __floats2half2_rn(vh.z, vh.w);
}

// ---------------- aggregation (fp16 gather) + fp16 A packing ----------------
// 128 threads: t<64 -> X16 4-feature chunk t ; t>=64 -> h16 chunk t-64
__global__ __launch_bounds__(128) void k_agg() {
    __shared__ int sidx[128];
    int n = blockIdx.x, t = threadIdx.x;
    int s0 = g_off[n], s1 = g_off[n + 1];
    const __half* basep = (t < 64) ? g_X16 : g_h16;
    int q = (t & 63) * 4;
    float ax = 0.f, ay = 0.f, az = 0.f, aw = 0.f;
    for (int bs = s0; bs < s1; bs += 128) {
        int cnt = min(128, s1 - bs);
        if (t < cnt) sidx[t] = g_srcSorted[bs + t];
        __syncthreads();
        int j = 0;
        for (; j + 4 <= cnt; j += 4) {
            #pragma unroll
            for (int u = 0; u < 4; u++) {
                const __half2* p = (const __half2*)(basep + (size_t)sidx[j + u] * 256 + q);
                float2 lo = __half22float2(p[0]);
                float2 hi2 = __half22float2(p[1]);
                ax += lo.x; ay += lo.y; az += hi2.x; aw += hi2.y;
            }
        }
        for (; j < cnt; j++) {
            const __half2* p = (const __half2*)(basep + (size_t)sidx[j] * 256 + q);
            float2 lo = __half22float2(p[0]);
            float2 hi2 = __half22float2(p[1]);
            ax += lo.x; ay += lo.y; az += hi2.x; aw += hi2.y;
        }
        __syncthreads();
    }
    int deg = s1 - s0;
    float inv = 1.f / (float)(deg > 0 ? deg : 1);
    const __half2* sp = (const __half2*)(basep + (size_t)n * 256 + q);
    __half2 self0 = sp[0], self1 = sp[1];
    size_t o = (size_t)n * 1024;
    int seg = (t < 64) ? 0 : 512;  // aggX 0-255, X 256-511, aggH 512-767, h 768-1023
    __half2* d0 = (__half2*)&g_Ab[o + seg + q];
    d0[0] = __floats2half2_rn(ax * inv, ay * inv);
    d0[1] = __floats2half2_rn(az * inv, aw * inv);
    __half2* d1 = (__half2*)&g_Ab[o + seg + 256 + q];
    d1[0] = self0;
    d1[1] = self1;
}

// ---------------- weight packing: col order j' = 4*e + gate ----------------
__global__ void k_packWt(const float* __restrict__ Wx_l, const float* __restrict__ Wx_r,
                         const float* __restrict__ Wh_l, const float* __restrict__ Wh_r,
                         const float* __restrict__ bx_l, const float* __restrict__ bh_l,
                         const float* __restrict__ bb) {
    int idx = blockIdx.x * blockDim.x + threadIdx.x;
    if (idx >= 1024 * 1024) return;
    int d = idx & 1023;      // K row
    int jp = idx >> 10;      // output col (interleaved)
    int e = jp >> 2, k = jp & 3;
    int seg = d >> 8, dd = d & 255;
    const float* src = (seg == 0) ? Wx_l : (seg == 1) ? Wx_r : (seg == 2) ? Wh_l : Wh_r;
    float w = src[k * 65536 + dd * 256 + e];
    g_Wtb[(size_t)jp * 1024 + d] = __float2half_rn(w);
    if (d == 0)
        g_bias[jp] = bx_l[k * 256 + e] + bh_l[k * 256 + e] + bb[k * 256 + e];
}

// ---------------- mma.sync fp16 GEMM (single pass, K=1024) + fused gates ----------------
#define BM 128
#define BN 128
#define NITER 16   // 1024 / 64
#define TILE_B 16384
#define STAGE_B (2 * TILE_B)
#define DYN_SMEM (3 * STAGE_B)

#define LDSM_X4(r0, r1, r2, r3, addr) \
    asm volatile("ldmatrix.sync.aligned.m8n8.x4.shared.b16 {%0,%1,%2,%3}, [%4];" \
                 : "=r"(r0), "=r"(r1), "=r"(r2), "=r"(r3) : "r"(addr))

#define MMA16816(d, a0, a1, a2, a3, b0, b1) \
    asm volatile("mma.sync.aligned.m16n8k16.row.col.f32.f16.f16.f32 " \
                 "{%0,%1,%2,%3}, {%4,%5,%6,%7}, {%8,%9}, {%0,%1,%2,%3};" \
                 : "+f"((d)[0]), "+f"((d)[1]), "+f"((d)[2]), "+f"((d)[3]) \
                 : "r"(a0), "r"(a1), "r"(a2), "r"(a3), "r"(b0), "r"(b1))

__device__ __forceinline__ void issue_tile(uint32_t sA, uint32_t sB, int m0, int n0,
                                           int it, int tid) {
    int kk = it * 64;
    #pragma unroll
    for (int i = 0; i < 4; i++) {
        int ch = tid + i * 256;
        int row = ch >> 3, c = ch & 7;
        uint32_t so = row * 128 + ((c ^ (row & 7)) << 4);
        const __half* ga = g_Ab + (size_t)(m0 + row) * 1024 + kk + c * 8;
        unsigned sz = (m0 + row < NN) ? 16u : 0u;
        asm volatile("cp.async.cg.shared.global [%0], [%1], 16, %2;"
                     :: "r"(sA + so), "l"(ga), "r"(sz));
        const __half* gb = g_Wtb + (size_t)(n0 + row) * 1024 + kk + c * 8;
        asm volatile("cp.async.cg.shared.global [%0], [%1], 16;"
                     :: "r"(sB + so), "l"(gb));
    }
}

__device__ __forceinline__ float fsigmoid(float x) { return 1.f / (1.f + __expf(-x)); }
__device__ __forceinline__ float ftanh(float x) {
    float e = __expf(-2.f * x);
    return (1.f - e) / (1.f + e);
}

__global__ __launch_bounds__(256, 2) void k_mma(const float* __restrict__ cptr,
                                                const float* __restrict__ wcp,
                                                float* __restrict__ out) {
    extern __shared__ char smem[];
    uint32_t sb = smem_u32(smem);
    int tid = threadIdx.x;
    int lane = tid & 31, wid = tid >> 5;
    int warp_m = wid & 3, warp_n = wid >> 2;
    int m0 = blockIdx.y * BM, n0 = blockIdx.x * BN;
    int e0 = n0 >> 2;  // 32 features per col tile

    float acc[2][8][4];
    #pragma unroll
    for (int i = 0; i < 2; i++)
        #pragma unroll
        for (int j = 0; j < 8; j++)
            #pragma unroll
            for (int r = 0; r < 4; r++) acc[i][j][r] = 0.f;

    uint32_t sA[3], sB[3];
    #pragma unroll
    for (int s = 0; s < 3; s++) { sA[s] = sb + s * STAGE_B; sB[s] = sA[s] + TILE_B; }

    issue_tile(sA[0], sB[0], m0, n0, 0, tid);
    asm volatile("cp.async.commit_group;" ::: "memory");
    issue_tile(sA[1], sB[1], m0, n0, 1, tid);
    asm volatile("cp.async.commit_group;" ::: "memory");

    // ldmatrix address invariants
    int rowA[2], rowA7[2];
    #pragma unroll
    for (int mi = 0; mi < 2; mi++) {
        int r = warp_m * 32 + mi * 16 + (lane & 15);
        rowA[mi] = r * 128;
        rowA7[mi] = r & 7;
    }
    int achk = lane >> 4;
    int local = lane & 7, quad = lane >> 3;
    int bchk = quad & 1;
    int rowB[4], rowB7[4];
    #pragma unroll
    for (int np = 0; np < 4; np++) {
        int r = warp_n * 64 + np * 16 + ((quad >> 1) << 3) + local;
        rowB[np] = r * 128;
        rowB7[np] = r & 7;
    }

    for (int it = 0; it < NITER; it++) {
        asm volatile("cp.async.wait_group 1;" ::: "memory");
        __syncthreads();
        if (it + 2 < NITER)
            issue_tile(sA[(it + 2) % 3], sB[(it + 2) % 3], m0, n0, it + 2, tid);
        asm volatile("cp.async.commit_group;" ::: "memory");
        int s = it % 3;
        uint32_t Ab = sA[s], Bb = sB[s];
        #pragma unroll
        for (int ks = 0; ks < 4; ks++) {
            uint32_t a[2][4];
            #pragma unroll
            for (int mi = 0; mi < 2; mi++) {
                uint32_t ad = Ab + rowA[mi] + ((((ks * 2 + achk)) ^ rowA7[mi]) << 4);
                LDSM_X4(a[mi][0], a[mi][1], a[mi][2], a[mi][3], ad);
            }
            #pragma unroll
            for (int np = 0; np < 4; np++) {
                uint32_t bd = Bb + rowB[np] + ((((ks * 2 + bchk)) ^ rowB7[np]) << 4);
                uint32_t t0, t1, t2, t3;
                LDSM_X4(t0, t1, t2, t3, bd);
                MMA16816(acc[0][np * 2],     a[0][0], a[0][1], a[0][2], a[0][3], t0, t1);
                MMA16816(acc[1][np * 2],     a[1][0], a[1][1], a[1][2], a[1][3], t0, t1);
                MMA16816(acc[0][np * 2 + 1], a[0][0], a[0][1], a[0][2], a[0][3], t2, t3);
                MMA16816(acc[1][np * 2 + 1], a[1][0], a[1][1], a[1][2], a[1][3], t2, t3);
            }
        }
    }
    __syncthreads();  // done with pipeline smem

    // -------- fused gate epilogue --------
    float* cbuf = (float*)smem;
    float* oO = (float*)(smem + 18432);
    float* oH = (float*)(smem + 36864);
    float* oC = (float*)(smem + 55296);
    float* wcb = (float*)(smem + 73728);

    for (int i = tid; i < 128 * 8; i += 256) {
        int r = i >> 3, q = i & 7;
        float4 v = make_float4(0.f, 0.f, 0.f, 0.f);
        if (m0 + r < NN) v = *(const float4*)(cptr + (size_t)(m0 + r) * 256 + e0 + q * 4);
        *(float4*)&cbuf[r * 36 + q * 4] = v;
    }
    if (tid < 96) wcb[tid] = wcp[(tid >> 5) * 256 + e0 + (tid & 31)];
    __syncthreads();

    int g = lane >> 2, t4 = lane & 3;
    #pragma unroll
    for (int mi = 0; mi < 2; mi++) {
        #pragma unroll
        for (int ni = 0; ni < 8; ni++) {
            int cloc = warp_n * 64 + ni * 8 + t4 * 2;
            float bias0 = __ldg(&g_bias[n0 + cloc]);
            float bias1 = __ldg(&g_bias[n0 + cloc + 1]);
            int eloc = warp_n * 16 + ni * 2 + (t4 >> 1);
            float wc0 = wcb[eloc], wc1 = wcb[32 + eloc], wc2 = wcb[64 + eloc];
            #pragma unroll
            for (int half = 0; half < 2; half++) {
                int row_loc = warp_m * 32 + mi * 16 + half * 8 + g;
                float v0 = acc[mi][ni][half * 2 + 0] + bias0;
                float v1 = acc[mi][ni][half * 2 + 1] + bias1;
                float p0 = __shfl_xor_sync(0xffffffffu, v0, 1);
                float p1 = __shfl_xor_sync(0xffffffffu, v1, 1);
                float pi, pf, pc, po;
                if ((t4 & 1) == 0) { pi = v0; pf = v1; pc = p0; po = p1; }
                else               { pi = p0; pf = p1; pc = v0; po = v1; }
                float cv = cbuf[row_loc * 36 + eloc];
                float I = fsigmoid(pi + wc0 * cv);
                float F = fsigmoid(pf + wc1 * cv);
                float T = ftanh(pc);
                float Cn = F * cv + I * T;
                float O = fsigmoid(po + wc2 * Cn);
                float Hn = O * ftanh(Cn);
                int so = row_loc * 36 + eloc;
                oO[so] = O; oH[so] = Hn; oC[so] = Cn;
            }
        }
    }
    __syncthreads();

    for (int i = tid; i < 128 * 8; i += 256) {
        int r = i >> 3, q = i & 7;
        int gr = m0 + r;
        if (gr < NN) {
            size_t go = (size_t)gr * 256 + e0 + q * 4;
            *(float4*)(out + go)                        = *(float4*)&oO[r * 36 + q * 4];
            *(float4*)(out + (size_t)NN * 256 + go)     = *(float4*)&oH[r * 36 + q * 4];
            *(float4*)(out + (size_t)2 * NN * 256 + go) = *(float4*)&oC[r * 36 + q * 4];
        }
    }
}

// ---------------- launch ----------------
extern "C" void kernel_launch(void* const* d_in, const int* in_sizes, int n_in,
                              void* d_out, int out_size) {
    const float* X    = (const float*)d_in[0];
    const void*  ei   = d_in[1];
    const float* h    = (const float*)d_in[2];
    const float* c    = (const float*)d_in[3];
    const float* Wx_l = (const float*)d_in[4];
    const float* bx_l = (const float*)d_in[5];
    const float* Wx_r = (const float*)d_in[6];
    const float* Wh_l = (const float*)d_in[7];
    const float* bh_l = (const float*)d_in[8];
    const float* Wh_r = (const float*)d_in[9];
    const float* wc   = (const float*)d_in[10];
    const float* b    = (const float*)d_in[11];
    float* out = (float*)d_out;

    static int inited = 0;
    static cudaStream_t s1;
    static cudaEvent_t ev0, ev1;
    if (!inited) {
        cudaFuncSetAttribute(k_mma, cudaFuncAttributeMaxDynamicSharedMemorySize, DYN_SMEM);
        cudaStreamCreateWithFlags(&s1, cudaStreamNonBlocking);
        cudaEventCreateWithFlags(&ev0, cudaEventDisableTiming);
        cudaEventCreateWithFlags(&ev1, cudaEventDisableTiming);
        inited = 1;
    }

    // fork: side stream does input conversions independent of edge pipeline
    cudaEventRecord(ev0, 0);
    cudaStreamWaitEvent(s1, ev0, 0);
    k_tofp16<<<(NN * 64 + 255) / 256, 256, 0, s1>>>(X, h);
    k_packWt<<<(1024 * 1024 + 255) / 256, 256, 0, s1>>>(Wx_l, Wx_r, Wh_l, Wh_r, bx_l, bh_l, b);
    cudaEventRecord(ev1, s1);

    // main stream: edge pipeline
    k_init<<<(NN + 255) / 256, 256>>>((const unsigned*)ei);
    k_convert<<<(EE + 255) / 256, 256>>>(ei);
    k_scan<<<1, 1024>>>();
    k_scatter<<<(EE + 255) / 256, 256>>>();

    // join: agg needs tofp16; mma needs packWt + agg
    cudaStreamWaitEvent(0, ev1, 0);
    k_agg<<<NN, 128>>>();
    k_mma<<<dim3(8, 79), 256, DYN_SMEM>>>(c, wc, out);
}